// round 1
// baseline (speedup 1.0000x reference)
#include <cuda_runtime.h>

// Spline1DInterpolant: out[b] = sum_i c[i] * u(|s_b + 2 - (i+1)|),
// with s = (x - a)/h, h = (b - a)/n, cubic B-spline basis u with support t<2.
// Only 4 consecutive coefficients contribute per query: i = floor(s) .. floor(s)+3.

static constexpr int B_QUERIES = 16384;

__device__ __forceinline__ float bspline_basis(float t) {
    // t is guaranteed in [0, 2] for our 4 taps.
    // inner (t<=1): 4 - 6t^2 + 3t^3 ; outer (1<t<=2): (2-t)^3
    float t2 = t * t;
    float inner = 4.0f - 6.0f * t2 + 3.0f * t2 * t;
    float om = 2.0f - t;
    float outer = om * om * om;
    return (t <= 1.0f) ? inner : outer;
}

__global__ void __launch_bounds__(128)
spline1d_kernel(const float* __restrict__ x,
                const float* __restrict__ a,
                const float* __restrict__ b,
                const float* __restrict__ n,
                const float* __restrict__ c,
                float* __restrict__ out,
                int nb, int nc) {
    int tid = blockIdx.x * blockDim.x + threadIdx.x;
    if (tid >= nb) return;

    // Replicate reference arithmetic exactly (fp32, true division).
    float a0 = __ldg(a);
    float h  = (__ldg(b) - a0) / __ldg(n);
    float s  = (__ldg(x + tid) - a0) / h;

    int i0 = (int)floorf(s);

    float sum = 0.0f;
#pragma unroll
    for (int k = 0; k < 4; k++) {
        int i = i0 + k;                       // coefficient index
        float jp1 = (float)(i + 1);           // reference's (i+1)
        float t = fabsf(s + 2.0f - jp1);      // same cancellation as reference
        float u = bspline_basis(t);
        // Guard (x in [0,1) => i in [0, nc-1], but stay safe at boundaries):
        if (i >= 0 && i < nc) {
            sum = fmaf(__ldg(c + i), u, sum);
        }
    }
    out[tid] = sum;
}

extern "C" void kernel_launch(void* const* d_in, const int* in_sizes, int n_in,
                              void* d_out, int out_size) {
    const float* x = (const float*)d_in[0];   // [B,1] fp32
    const float* a = (const float*)d_in[1];   // [1]
    const float* b = (const float*)d_in[2];   // [1]
    const float* n = (const float*)d_in[3];   // [1]
    const float* c = (const float*)d_in[4];   // [C]
    float* out = (float*)d_out;

    int nb = in_sizes[0];      // 16384
    int nc = in_sizes[4];      // 4096

    const int threads = 128;
    int blocks = (nb + threads - 1) / threads;   // 128 blocks -> ~one wave on 148 SMs
    spline1d_kernel<<<blocks, threads>>>(x, a, b, n, c, out, nb, nc);
}

// round 2
// speedup vs baseline: 1.0153x; 1.0153x over previous
#include <cuda_runtime.h>

// Spline1DInterpolant: out[q] = sum_i c[i] * u(|s_q + 2 - (i+1)|),
// s = (x - a)/h, h = (b - a)/n. Cubic B-spline: support t < 2 => exactly 4 taps
// per query: i = floor(s) .. floor(s)+3.
//
// Latency-bound kernel: 4 queries per thread (float4 x / out), 32-thread blocks
// so the ~4096 threads spread one short dependency chain per SM across the chip.

__device__ __forceinline__ float bspline_basis(float t) {
    // t in [0,2]; inner (t<=1): 4 - 6t^2 + 3t^3 ; outer: (2-t)^3
    float t2 = t * t;
    float inner = 4.0f - 6.0f * t2 + 3.0f * t2 * t;
    float om = 2.0f - t;
    float outer = om * om * om;
    return (t <= 1.0f) ? inner : outer;
}

__device__ __forceinline__ float eval_query(float xq, float a0, float h,
                                            const float* __restrict__ c, int nc) {
    float s = (xq - a0) / h;          // reference-exact formulation
    int i0 = (int)floorf(s);
    float sum = 0.0f;
#pragma unroll
    for (int k = 0; k < 4; k++) {
        int i = i0 + k;
        float t = fabsf(s + 2.0f - (float)(i + 1));
        float u = bspline_basis(t);
        if ((unsigned)i < (unsigned)nc) {
            sum = fmaf(__ldg(c + i), u, sum);
        }
    }
    return sum;
}

__global__ void __launch_bounds__(32)
spline1d_vec4(const float4* __restrict__ x4,
              const float* __restrict__ a,
              const float* __restrict__ b,
              const float* __restrict__ n,
              const float* __restrict__ c,
              float4* __restrict__ out4,
              int nb4, int nc) {
    int tid = blockIdx.x * 32 + threadIdx.x;
    if (tid >= nb4) return;

    // Independent loads issue together: x vector + broadcast scalars.
    float4 xv = __ldg(x4 + tid);
    float a0 = __ldg(a);
    float h  = (__ldg(b) - a0) / __ldg(n);

    float4 r;
    r.x = eval_query(xv.x, a0, h, c, nc);
    r.y = eval_query(xv.y, a0, h, c, nc);
    r.z = eval_query(xv.z, a0, h, c, nc);
    r.w = eval_query(xv.w, a0, h, c, nc);

    out4[tid] = r;
}

// Scalar tail (only launched if nb % 4 != 0; never for the fixed B=16384 shape).
__global__ void __launch_bounds__(32)
spline1d_tail(const float* __restrict__ x,
              const float* __restrict__ a,
              const float* __restrict__ b,
              const float* __restrict__ n,
              const float* __restrict__ c,
              float* __restrict__ out,
              int start, int nb, int nc) {
    int tid = start + blockIdx.x * 32 + threadIdx.x;
    if (tid >= nb) return;
    float a0 = __ldg(a);
    float h  = (__ldg(b) - a0) / __ldg(n);
    out[tid] = eval_query(__ldg(x + tid), a0, h, c, nc);
}

extern "C" void kernel_launch(void* const* d_in, const int* in_sizes, int n_in,
                              void* d_out, int out_size) {
    const float* x = (const float*)d_in[0];   // [B,1] fp32
    const float* a = (const float*)d_in[1];   // [1]
    const float* b = (const float*)d_in[2];   // [1]
    const float* n = (const float*)d_in[3];   // [1]
    const float* c = (const float*)d_in[4];   // [C]
    float* out = (float*)d_out;

    int nb = in_sizes[0];      // 16384
    int nc = in_sizes[4];      // 4096

    int nb4 = nb >> 2;
    if (nb4 > 0) {
        int blocks = (nb4 + 31) / 32;          // 128 blocks of 1 warp each
        spline1d_vec4<<<blocks, 32>>>((const float4*)x, a, b, n, c,
                                      (float4*)out, nb4, nc);
    }
    int rem = nb & 3;
    if (rem) {
        spline1d_tail<<<1, 32>>>(x, a, b, n, c, out, nb4 << 2, nb, nc);
    }
}